// round 10
// baseline (speedup 1.0000x reference)
#include <cuda_runtime.h>
#include <stdint.h>
#include <math.h>

#define B_ 8
#define S_ 1024
#define H_ 16
#define D_ 64
#define M_ 1024
#define HD (H_ * D_)

#define KSTR 68  // K smem stride: B-frag bank = 4g+q  -> conflict-free
#define VSTR 72  // V smem stride: B-frag bank = 8q+g  -> conflict-free
#define PSTR 68  // P smem stride: A-frag bank = 4g+q  -> conflict-free

__device__ unsigned char g_rowmask[B_ * S_];
__device__ unsigned char g_colmask[B_ * S_];

__global__ void zero_masks_kernel() {
    int i = blockIdx.x * blockDim.x + threadIdx.x;
    if (i < B_ * S_) {
        g_rowmask[i] = 0;
        g_colmask[i] = 0;
    }
}

__global__ void scatter_masks_kernel(const int* __restrict__ qm_b, const int* __restrict__ qm_s,
                                     const int* __restrict__ km_b, const int* __restrict__ km_s) {
    int i = blockIdx.x * blockDim.x + threadIdx.x;
    if (i < M_) {
        g_rowmask[qm_b[i] * S_ + qm_s[i]] = 1;
        g_colmask[km_b[i] * S_ + km_s[i]] = 1;
    }
}

__device__ __forceinline__ unsigned f2tf(float x) {
    unsigned u;
    asm("cvt.rna.tf32.f32 %0, %1;" : "=r"(u) : "f"(x));
    return u;
}

__device__ __forceinline__ void mma8(float& c0, float& c1, float& c2, float& c3,
                                     unsigned a0, unsigned a1, unsigned a2, unsigned a3,
                                     unsigned b0, unsigned b1) {
    asm volatile(
        "mma.sync.aligned.m16n8k8.row.col.f32.tf32.tf32.f32 "
        "{%0,%1,%2,%3}, {%4,%5,%6,%7}, {%8,%9}, {%0,%1,%2,%3};"
        : "+f"(c0), "+f"(c1), "+f"(c2), "+f"(c3)
        : "r"(a0), "r"(a1), "r"(a2), "r"(a3), "r"(b0), "r"(b1));
}

__device__ __forceinline__ void cp16(const void* smem_dst, const void* gmem_src) {
    unsigned daddr = (unsigned)__cvta_generic_to_shared(smem_dst);
    asm volatile("cp.async.ca.shared.global [%0], [%1], 16;" :: "r"(daddr), "l"(gmem_src));
}

// Flash attention, tf32 mma.sync, 32-row warp tiles, cp.async double-buffered
// K/V staging (raw fp32 in smem; tf32 rounding at fragment build — values
// bit-identical to the synchronous version).
__global__ __launch_bounds__(128, 2) void attn_kernel(const float* __restrict__ Q,
                                                      const float* __restrict__ K,
                                                      const float* __restrict__ V,
                                                      float* __restrict__ O) {
    extern __shared__ float smem[];
    float* Kbuf[2] = { smem, smem + 64 * KSTR };
    float* Vbuf[2] = { smem + 2 * 64 * KSTR, smem + 2 * 64 * KSTR + 64 * VSTR };
    float* Ps = smem + 2 * 64 * KSTR + 2 * 64 * VSTR;          // 4 * 32 * PSTR
    unsigned char* CmB = (unsigned char*)(Ps + 4 * 32 * PSTR); // 2 * 64

    const int bid = blockIdx.x;
    const int qt = bid & 7;
    const int h  = (bid >> 3) & 15;
    const int b  = bid >> 7;
    const int tid = threadIdx.x;
    const int w = tid >> 5, lane = tid & 31;
    const int g = lane >> 2, q = lane & 3;

    float* Pw = Ps + w * (32 * PSTR);
    const int row0 = qt * 128 + w * 32;

    const float* Kb = K + (size_t)b * S_ * HD + h * D_;
    const float* Vb = V + ((size_t)b * H_ + h) * S_ * D_;

    // ---- prologue: stage tile 0 into buffer 0 ----
    {
        #pragma unroll
        for (int i = 0; i < 8; ++i) {
            int idx = i * 128 + tid;
            int c4 = idx >> 6, s = idx & 63;
            cp16(&Kbuf[0][s * KSTR + 4 * c4], Kb + (size_t)s * HD + 4 * c4);
            cp16(&Vbuf[0][s * VSTR + 4 * c4], Vb + (size_t)s * D_ + 4 * c4);
        }
        if (tid < 4)
            cp16(CmB + 16 * tid, g_colmask + b * S_ + 16 * tid);
        asm volatile("cp.async.commit_group;");
    }

    // ---- Q fragments for both row-tiles (scale 1/8 folded, tf32 RNA) ----
    unsigned qf[2][8][4];
    #pragma unroll
    for (int t = 0; t < 2; ++t) {
        const float* Qb = Q + ((size_t)(b * S_ + row0 + 16 * t + g)) * HD + h * D_;
        #pragma unroll
        for (int ks = 0; ks < 8; ++ks) {
            qf[t][ks][0] = f2tf(Qb[ks * 8 + q] * 0.125f);
            qf[t][ks][1] = f2tf(Qb[(size_t)8 * HD + ks * 8 + q] * 0.125f);
            qf[t][ks][2] = f2tf(Qb[ks * 8 + q + 4] * 0.125f);
            qf[t][ks][3] = f2tf(Qb[(size_t)8 * HD + ks * 8 + q + 4] * 0.125f);
        }
    }
    int rm[2][2];
    #pragma unroll
    for (int t = 0; t < 2; ++t) {
        rm[t][0] = g_rowmask[b * S_ + row0 + 16 * t + g];
        rm[t][1] = g_rowmask[b * S_ + row0 + 16 * t + g + 8];
    }

    float o_[2][8][4];
    #pragma unroll
    for (int t = 0; t < 2; ++t)
        #pragma unroll
        for (int nt = 0; nt < 8; ++nt)
            o_[t][nt][0] = o_[t][nt][1] = o_[t][nt][2] = o_[t][nt][3] = 0.f;
    float m_[2][2], l_[2][2];
    #pragma unroll
    for (int t = 0; t < 2; ++t) { m_[t][0] = m_[t][1] = -INFINITY; l_[t][0] = l_[t][1] = 0.f; }

    for (int kt = 0; kt < 16; ++kt) {
        const int cur = kt & 1;
        asm volatile("cp.async.wait_group 0;");
        __syncthreads();  // current tile visible to all; prev buffer reads done

        // ---- prefetch next tile into the other buffer ----
        if (kt + 1 < 16) {
            const int nxt = cur ^ 1;
            #pragma unroll
            for (int i = 0; i < 8; ++i) {
                int idx = i * 128 + tid;
                int c4 = idx >> 6, s = idx & 63;
                cp16(&Kbuf[nxt][s * KSTR + 4 * c4],
                     Kb + (size_t)((kt + 1) * 64 + s) * HD + 4 * c4);
                cp16(&Vbuf[nxt][s * VSTR + 4 * c4],
                     Vb + (size_t)((kt + 1) * 64 + s) * D_ + 4 * c4);
            }
            if (tid < 4)
                cp16(CmB + 64 * nxt + 16 * tid,
                     g_colmask + b * S_ + (kt + 1) * 64 + 16 * tid);
            asm volatile("cp.async.commit_group;");
        }

        const float* Ksb = Kbuf[cur];
        const float* Vsb = Vbuf[cur];
        const unsigned char* Cm = CmB + 64 * cur;

        // ---- S = Q K^T : B-frags shared by both row-tiles (cvt at build) ----
        float s0[8][4], s1[8][4];
        #pragma unroll
        for (int nt = 0; nt < 8; ++nt) {
            s0[nt][0] = s0[nt][1] = s0[nt][2] = s0[nt][3] = 0.f;
            s1[nt][0] = s1[nt][1] = s1[nt][2] = s1[nt][3] = 0.f;
        }
        #pragma unroll
        for (int ks = 0; ks < 8; ++ks) {
            #pragma unroll
            for (int nt = 0; nt < 8; ++nt) {
                const float* kp = &Ksb[(nt * 8 + g) * KSTR + ks * 8 + q];
                unsigned b0 = f2tf(kp[0]);
                unsigned b1 = f2tf(kp[4]);
                mma8(s0[nt][0], s0[nt][1], s0[nt][2], s0[nt][3],
                     qf[0][ks][0], qf[0][ks][1], qf[0][ks][2], qf[0][ks][3], b0, b1);
                mma8(s1[nt][0], s1[nt][1], s1[nt][2], s1[nt][3],
                     qf[1][ks][0], qf[1][ks][1], qf[1][ks][2], qf[1][ks][3], b0, b1);
            }
        }

        // ---- mask + online softmax ----
        float al[2][2];
        #pragma unroll
        for (int t = 0; t < 2; ++t) {
            float (*s_)[4] = t ? s1 : s0;
            float tm0 = -INFINITY, tm1 = -INFINITY;
            #pragma unroll
            for (int nt = 0; nt < 8; ++nt) {
                unsigned cc = *(const unsigned short*)(Cm + nt * 8 + 2 * q);
                int c0 = (int)(cc & 0xFFu), c1 = (int)(cc >> 8);
                if (rm[t][0] | c0) s_[nt][0] = -1e10f;
                if (rm[t][0] | c1) s_[nt][1] = -1e10f;
                if (rm[t][1] | c0) s_[nt][2] = -1e10f;
                if (rm[t][1] | c1) s_[nt][3] = -1e10f;
                tm0 = fmaxf(tm0, fmaxf(s_[nt][0], s_[nt][1]));
                tm1 = fmaxf(tm1, fmaxf(s_[nt][2], s_[nt][3]));
            }
            tm0 = fmaxf(tm0, __shfl_xor_sync(0xffffffffu, tm0, 1));
            tm0 = fmaxf(tm0, __shfl_xor_sync(0xffffffffu, tm0, 2));
            tm1 = fmaxf(tm1, __shfl_xor_sync(0xffffffffu, tm1, 1));
            tm1 = fmaxf(tm1, __shfl_xor_sync(0xffffffffu, tm1, 2));
            float mn0 = fmaxf(m_[t][0], tm0), mn1 = fmaxf(m_[t][1], tm1);
            float a0 = __expf(m_[t][0] - mn0), a1 = __expf(m_[t][1] - mn1);
            float ps0 = 0.f, ps1 = 0.f;
            #pragma unroll
            for (int nt = 0; nt < 8; ++nt) {
                s_[nt][0] = __expf(s_[nt][0] - mn0);
                s_[nt][1] = __expf(s_[nt][1] - mn0);
                s_[nt][2] = __expf(s_[nt][2] - mn1);
                s_[nt][3] = __expf(s_[nt][3] - mn1);
                ps0 += s_[nt][0] + s_[nt][1];
                ps1 += s_[nt][2] + s_[nt][3];
            }
            ps0 += __shfl_xor_sync(0xffffffffu, ps0, 1);
            ps0 += __shfl_xor_sync(0xffffffffu, ps0, 2);
            ps1 += __shfl_xor_sync(0xffffffffu, ps1, 1);
            ps1 += __shfl_xor_sync(0xffffffffu, ps1, 2);
            l_[t][0] = l_[t][0] * a0 + ps0;
            l_[t][1] = l_[t][1] * a1 + ps1;
            m_[t][0] = mn0; m_[t][1] = mn1;
            al[t][0] = a0; al[t][1] = a1;
        }
        #pragma unroll
        for (int t = 0; t < 2; ++t)
            #pragma unroll
            for (int nt = 0; nt < 8; ++nt) {
                o_[t][nt][0] *= al[t][0]; o_[t][nt][1] *= al[t][0];
                o_[t][nt][2] *= al[t][1]; o_[t][nt][3] *= al[t][1];
            }

        // ---- P -> warp-private smem (tf32 RNA), consume as A-frags ----
        __syncwarp();
        #pragma unroll
        for (int t = 0; t < 2; ++t) {
            float (*s_)[4] = t ? s1 : s0;
            #pragma unroll
            for (int nt = 0; nt < 8; ++nt) {
                uint2 lo = make_uint2(f2tf(s_[nt][0]), f2tf(s_[nt][1]));
                uint2 hi = make_uint2(f2tf(s_[nt][2]), f2tf(s_[nt][3]));
                *(uint2*)&Pw[(16 * t + g) * PSTR + 8 * nt + 2 * q] = lo;
                *(uint2*)&Pw[(16 * t + g + 8) * PSTR + 8 * nt + 2 * q] = hi;
            }
        }
        __syncwarp();

        // ---- O += P V ----
        #pragma unroll
        for (int ks = 0; ks < 8; ++ks) {
            unsigned a[2][4];
            #pragma unroll
            for (int t = 0; t < 2; ++t) {
                const float* pp = &Pw[(16 * t + g) * PSTR + 8 * ks + q];
                a[t][0] = __float_as_uint(pp[0]);
                a[t][1] = __float_as_uint(pp[8 * PSTR]);
                a[t][2] = __float_as_uint(pp[4]);
                a[t][3] = __float_as_uint(pp[8 * PSTR + 4]);
            }
            #pragma unroll
            for (int nt = 0; nt < 8; ++nt) {
                const float* vp = &Vsb[(ks * 8 + q) * VSTR + 8 * nt + g];
                unsigned b0 = f2tf(vp[0]);
                unsigned b1 = f2tf(vp[4 * VSTR]);
                mma8(o_[0][nt][0], o_[0][nt][1], o_[0][nt][2], o_[0][nt][3],
                     a[0][0], a[0][1], a[0][2], a[0][3], b0, b1);
                mma8(o_[1][nt][0], o_[1][nt][1], o_[1][nt][2], o_[1][nt][3],
                     a[1][0], a[1][1], a[1][2], a[1][3], b0, b1);
            }
        }
    }

    // ---- epilogue: normalize + store; O is (B,H,S,D) ----
    float* Ob = O + (((size_t)b * H_ + h) * S_ + row0) * D_;
    #pragma unroll
    for (int t = 0; t < 2; ++t) {
        float il0 = 1.f / l_[t][0], il1 = 1.f / l_[t][1];
        float* r_lo = Ob + (size_t)(16 * t + g) * D_;
        float* r_hi = Ob + (size_t)(16 * t + g + 8) * D_;
        #pragma unroll
        for (int nt = 0; nt < 8; ++nt) {
            *(float2*)(r_lo + 8 * nt + 2 * q) =
                make_float2(o_[t][nt][0] * il0, o_[t][nt][1] * il0);
            *(float2*)(r_hi + 8 * nt + 2 * q) =
                make_float2(o_[t][nt][2] * il1, o_[t][nt][3] * il1);
        }
    }
}

static const int SMEM_BYTES = (2 * 64 * KSTR + 2 * 64 * VSTR + 4 * 32 * PSTR) * 4 + 128;

extern "C" void kernel_launch(void* const* d_in, const int* in_sizes, int n_in,
                              void* d_out, int out_size) {
    const float* Q = (const float*)d_in[0];
    const float* K = (const float*)d_in[1];
    const float* V = (const float*)d_in[2];
    const int* qm_b = (const int*)d_in[3];
    const int* qm_s = (const int*)d_in[4];
    const int* km_b = (const int*)d_in[5];
    const int* km_s = (const int*)d_in[6];
    float* O = (float*)d_out;

    cudaFuncSetAttribute(attn_kernel, cudaFuncAttributeMaxDynamicSharedMemorySize, SMEM_BYTES);

    zero_masks_kernel<<<(B_ * S_ + 255) / 256, 256>>>();
    scatter_masks_kernel<<<(M_ + 255) / 256, 256>>>(qm_b, qm_s, km_b, km_s);
    attn_kernel<<<B_ * H_ * (S_ / 128), 128, SMEM_BYTES>>>(Q, K, V, O);
}

// round 13
// speedup vs baseline: 1.0055x; 1.0055x over previous
#include <cuda_runtime.h>
#include <stdint.h>
#include <math.h>

#define B_ 8
#define S_ 1024
#define H_ 16
#define D_ 64
#define M_ 1024
#define HD (H_ * D_)
#define NELEM (B_ * S_ * H_ * D_)

#define KSTR 68  // K smem stride: B-frag bank = 4g+q  -> conflict-free
#define VSTR 72  // V smem stride: B-frag bank = 8q+g  -> conflict-free
#define PSTR 68  // P smem stride: A-frag bank = 4g+q  -> conflict-free

__device__ unsigned char g_rowmask[B_ * S_];
__device__ unsigned char g_colmask[B_ * S_];
__device__ float g_Ktf[NELEM];  // tf32-rounded K
__device__ float g_Vtf[NELEM];  // tf32-rounded V

__global__ void zero_masks_kernel() {
    int i = blockIdx.x * blockDim.x + threadIdx.x;
    if (i < B_ * S_) {
        g_rowmask[i] = 0;
        g_colmask[i] = 0;
    }
}

__global__ void scatter_masks_kernel(const int* __restrict__ qm_b, const int* __restrict__ qm_s,
                                     const int* __restrict__ km_b, const int* __restrict__ km_s) {
    int i = blockIdx.x * blockDim.x + threadIdx.x;
    if (i < M_) {
        g_rowmask[qm_b[i] * S_ + qm_s[i]] = 1;
        g_colmask[km_b[i] * S_ + km_s[i]] = 1;
    }
}

__device__ __forceinline__ unsigned f2tf(float x) {
    unsigned u;
    asm("cvt.rna.tf32.f32 %0, %1;" : "=r"(u) : "f"(x));
    return u;
}

// Pre-round a tensor to tf32 (RNA), vectorized.
__global__ void tf32_round_kernel(const float4* __restrict__ src, uint4* __restrict__ dst) {
    int i = blockIdx.x * blockDim.x + threadIdx.x;
    if (i < NELEM / 4) {
        float4 v = src[i];
        uint4 u;
        u.x = f2tf(v.x); u.y = f2tf(v.y); u.z = f2tf(v.z); u.w = f2tf(v.w);
        dst[i] = u;
    }
}

__device__ __forceinline__ void mma8(float& c0, float& c1, float& c2, float& c3,
                                     unsigned a0, unsigned a1, unsigned a2, unsigned a3,
                                     unsigned b0, unsigned b1) {
    asm volatile(
        "mma.sync.aligned.m16n8k8.row.col.f32.tf32.tf32.f32 "
        "{%0,%1,%2,%3}, {%4,%5,%6,%7}, {%8,%9}, {%0,%1,%2,%3};"
        : "+f"(c0), "+f"(c1), "+f"(c2), "+f"(c3)
        : "r"(a0), "r"(a1), "r"(a2), "r"(a3), "r"(b0), "r"(b1));
}

__device__ __forceinline__ void cp16(const void* smem_dst, const void* gmem_src) {
    unsigned daddr = (unsigned)__cvta_generic_to_shared(smem_dst);
    asm volatile("cp.async.ca.shared.global [%0], [%1], 16;" :: "r"(daddr), "l"(gmem_src));
}

// Flash attention, tf32 mma.sync, 32-row warp tiles, cp.async double-buffered
// staging of PRE-ROUNDED K/V (no cvt in the hot loops).
__global__ __launch_bounds__(128, 2) void attn_kernel(const float* __restrict__ Q,
                                                      float* __restrict__ O) {
    extern __shared__ float smem[];
    float* Kbuf[2] = { smem, smem + 64 * KSTR };
    float* Vbuf[2] = { smem + 2 * 64 * KSTR, smem + 2 * 64 * KSTR + 64 * VSTR };
    float* Ps = smem + 2 * 64 * KSTR + 2 * 64 * VSTR;          // 4 * 32 * PSTR
    unsigned char* CmB = (unsigned char*)(Ps + 4 * 32 * PSTR); // 2 * 64

    const int bid = blockIdx.x;
    const int qt = bid & 7;
    const int h  = (bid >> 3) & 15;
    const int b  = bid >> 7;
    const int tid = threadIdx.x;
    const int w = tid >> 5, lane = tid & 31;
    const int g = lane >> 2, q = lane & 3;

    float* Pw = Ps + w * (32 * PSTR);
    const int row0 = qt * 128 + w * 32;

    const float* Kb = g_Ktf + (size_t)b * S_ * HD + h * D_;
    const float* Vb = g_Vtf + ((size_t)b * H_ + h) * S_ * D_;

    // ---- prologue: stage tile 0 into buffer 0 ----
    {
        #pragma unroll
        for (int i = 0; i < 8; ++i) {
            int idx = i * 128 + tid;
            int c4 = idx >> 6, s = idx & 63;
            cp16(&Kbuf[0][s * KSTR + 4 * c4], Kb + (size_t)s * HD + 4 * c4);
            cp16(&Vbuf[0][s * VSTR + 4 * c4], Vb + (size_t)s * D_ + 4 * c4);
        }
        if (tid < 4)
            cp16(CmB + 16 * tid, g_colmask + b * S_ + 16 * tid);
        asm volatile("cp.async.commit_group;");
    }

    // ---- Q fragments for both row-tiles (scale 1/8 folded, tf32 RNA) ----
    unsigned qf[2][8][4];
    #pragma unroll
    for (int t = 0; t < 2; ++t) {
        const float* Qb = Q + ((size_t)(b * S_ + row0 + 16 * t + g)) * HD + h * D_;
        #pragma unroll
        for (int ks = 0; ks < 8; ++ks) {
            qf[t][ks][0] = f2tf(Qb[ks * 8 + q] * 0.125f);
            qf[t][ks][1] = f2tf(Qb[(size_t)8 * HD + ks * 8 + q] * 0.125f);
            qf[t][ks][2] = f2tf(Qb[ks * 8 + q + 4] * 0.125f);
            qf[t][ks][3] = f2tf(Qb[(size_t)8 * HD + ks * 8 + q + 4] * 0.125f);
        }
    }
    int rm[2][2];
    #pragma unroll
    for (int t = 0; t < 2; ++t) {
        rm[t][0] = g_rowmask[b * S_ + row0 + 16 * t + g];
        rm[t][1] = g_rowmask[b * S_ + row0 + 16 * t + g + 8];
    }

    float o_[2][8][4];
    #pragma unroll
    for (int t = 0; t < 2; ++t)
        #pragma unroll
        for (int nt = 0; nt < 8; ++nt)
            o_[t][nt][0] = o_[t][nt][1] = o_[t][nt][2] = o_[t][nt][3] = 0.f;
    float m_[2][2], l_[2][2];
    #pragma unroll
    for (int t = 0; t < 2; ++t) { m_[t][0] = m_[t][1] = -INFINITY; l_[t][0] = l_[t][1] = 0.f; }

    for (int kt = 0; kt < 16; ++kt) {
        const int cur = kt & 1;
        asm volatile("cp.async.wait_group 0;");
        __syncthreads();  // current tile visible; prev buffer reads done

        // ---- prefetch next tile into the other buffer ----
        if (kt + 1 < 16) {
            const int nxt = cur ^ 1;
            #pragma unroll
            for (int i = 0; i < 8; ++i) {
                int idx = i * 128 + tid;
                int c4 = idx >> 6, s = idx & 63;
                cp16(&Kbuf[nxt][s * KSTR + 4 * c4],
                     Kb + (size_t)((kt + 1) * 64 + s) * HD + 4 * c4);
                cp16(&Vbuf[nxt][s * VSTR + 4 * c4],
                     Vb + (size_t)((kt + 1) * 64 + s) * D_ + 4 * c4);
            }
            if (tid < 4)
                cp16(CmB + 64 * nxt + 16 * tid,
                     g_colmask + b * S_ + (kt + 1) * 64 + 16 * tid);
            asm volatile("cp.async.commit_group;");
        }

        const float* Ksb = Kbuf[cur];
        const float* Vsb = Vbuf[cur];
        const unsigned char* Cm = CmB + 64 * cur;

        // ---- S = Q K^T : B-frags shared by both row-tiles (no cvt!) ----
        float s0[8][4], s1[8][4];
        #pragma unroll
        for (int nt = 0; nt < 8; ++nt) {
            s0[nt][0] = s0[nt][1] = s0[nt][2] = s0[nt][3] = 0.f;
            s1[nt][0] = s1[nt][1] = s1[nt][2] = s1[nt][3] = 0.f;
        }
        #pragma unroll
        for (int ks = 0; ks < 8; ++ks) {
            #pragma unroll
            for (int nt = 0; nt < 8; ++nt) {
                const float* kp = &Ksb[(nt * 8 + g) * KSTR + ks * 8 + q];
                unsigned b0 = __float_as_uint(kp[0]);
                unsigned b1 = __float_as_uint(kp[4]);
                mma8(s0[nt][0], s0[nt][1], s0[nt][2], s0[nt][3],
                     qf[0][ks][0], qf[0][ks][1], qf[0][ks][2], qf[0][ks][3], b0, b1);
                mma8(s1[nt][0], s1[nt][1], s1[nt][2], s1[nt][3],
                     qf[1][ks][0], qf[1][ks][1], qf[1][ks][2], qf[1][ks][3], b0, b1);
            }
        }

        // ---- mask + online softmax ----
        float al[2][2];
        #pragma unroll
        for (int t = 0; t < 2; ++t) {
            float (*s_)[4] = t ? s1 : s0;
            float tm0 = -INFINITY, tm1 = -INFINITY;
            #pragma unroll
            for (int nt = 0; nt < 8; ++nt) {
                unsigned cc = *(const unsigned short*)(Cm + nt * 8 + 2 * q);
                int c0 = (int)(cc & 0xFFu), c1 = (int)(cc >> 8);
                if (rm[t][0] | c0) s_[nt][0] = -1e10f;
                if (rm[t][0] | c1) s_[nt][1] = -1e10f;
                if (rm[t][1] | c0) s_[nt][2] = -1e10f;
                if (rm[t][1] | c1) s_[nt][3] = -1e10f;
                tm0 = fmaxf(tm0, fmaxf(s_[nt][0], s_[nt][1]));
                tm1 = fmaxf(tm1, fmaxf(s_[nt][2], s_[nt][3]));
            }
            tm0 = fmaxf(tm0, __shfl_xor_sync(0xffffffffu, tm0, 1));
            tm0 = fmaxf(tm0, __shfl_xor_sync(0xffffffffu, tm0, 2));
            tm1 = fmaxf(tm1, __shfl_xor_sync(0xffffffffu, tm1, 1));
            tm1 = fmaxf(tm1, __shfl_xor_sync(0xffffffffu, tm1, 2));
            float mn0 = fmaxf(m_[t][0], tm0), mn1 = fmaxf(m_[t][1], tm1);
            float a0 = __expf(m_[t][0] - mn0), a1 = __expf(m_[t][1] - mn1);
            float ps0 = 0.f, ps1 = 0.f;
            #pragma unroll
            for (int nt = 0; nt < 8; ++nt) {
                s_[nt][0] = __expf(s_[nt][0] - mn0);
                s_[nt][1] = __expf(s_[nt][1] - mn0);
                s_[nt][2] = __expf(s_[nt][2] - mn1);
                s_[nt][3] = __expf(s_[nt][3] - mn1);
                ps0 += s_[nt][0] + s_[nt][1];
                ps1 += s_[nt][2] + s_[nt][3];
            }
            ps0 += __shfl_xor_sync(0xffffffffu, ps0, 1);
            ps0 += __shfl_xor_sync(0xffffffffu, ps0, 2);
            ps1 += __shfl_xor_sync(0xffffffffu, ps1, 1);
            ps1 += __shfl_xor_sync(0xffffffffu, ps1, 2);
            l_[t][0] = l_[t][0] * a0 + ps0;
            l_[t][1] = l_[t][1] * a1 + ps1;
            m_[t][0] = mn0; m_[t][1] = mn1;
            al[t][0] = a0; al[t][1] = a1;
        }
        #pragma unroll
        for (int t = 0; t < 2; ++t)
            #pragma unroll
            for (int nt = 0; nt < 8; ++nt) {
                o_[t][nt][0] *= al[t][0]; o_[t][nt][1] *= al[t][0];
                o_[t][nt][2] *= al[t][1]; o_[t][nt][3] *= al[t][1];
            }

        // ---- P -> warp-private smem (tf32 RNA), consume as A-frags ----
        __syncwarp();
        #pragma unroll
        for (int t = 0; t < 2; ++t) {
            float (*s_)[4] = t ? s1 : s0;
            #pragma unroll
            for (int nt = 0; nt < 8; ++nt) {
                uint2 lo = make_uint2(f2tf(s_[nt][0]), f2tf(s_[nt][1]));
                uint2 hi = make_uint2(f2tf(s_[nt][2]), f2tf(s_[nt][3]));
                *(uint2*)&Pw[(16 * t + g) * PSTR + 8 * nt + 2 * q] = lo;
                *(uint2*)&Pw[(16 * t + g + 8) * PSTR + 8 * nt + 2 * q] = hi;
            }
        }
        __syncwarp();

        // ---- O += P V (no cvt on V) ----
        #pragma unroll
        for (int ks = 0; ks < 8; ++ks) {
            unsigned a[2][4];
            #pragma unroll
            for (int t = 0; t < 2; ++t) {
                const float* pp = &Pw[(16 * t + g) * PSTR + 8 * ks + q];
                a[t][0] = __float_as_uint(pp[0]);
                a[t][1] = __float_as_uint(pp[8 * PSTR]);
                a[t][2] = __float_as_uint(pp[4]);
                a[t][3] = __float_as_uint(pp[8 * PSTR + 4]);
            }
            #pragma unroll
            for (int nt = 0; nt < 8; ++nt) {
                const float* vp = &Vsb[(ks * 8 + q) * VSTR + 8 * nt + g];
                unsigned b0 = __float_as_uint(vp[0]);
                unsigned b1 = __float_as_uint(vp[4 * VSTR]);
                mma8(o_[0][nt][0], o_[0][nt][1], o_[0][nt][2], o_[0][nt][3],
                     a[0][0], a[0][1], a[0][2], a[0][3], b0, b1);
                mma8(o_[1][nt][0], o_[1][nt][1], o_[1][nt][2], o_[1][nt][3],
                     a[1][0], a[1][1], a[1][2], a[1][3], b0, b1);
            }
        }
    }

    // ---- epilogue: normalize + store; O is (B,H,S,D) ----
    float* Ob = O + (((size_t)b * H_ + h) * S_ + row0) * D_;
    #pragma unroll
    for (int t = 0; t < 2; ++t) {
        float il0 = 1.f / l_[t][0], il1 = 1.f / l_[t][1];
        float* r_lo = Ob + (size_t)(16 * t + g) * D_;
        float* r_hi = Ob + (size_t)(16 * t + g + 8) * D_;
        #pragma unroll
        for (int nt = 0; nt < 8; ++nt) {
            *(float2*)(r_lo + 8 * nt + 2 * q) =
                make_float2(o_[t][nt][0] * il0, o_[t][nt][1] * il0);
            *(float2*)(r_hi + 8 * nt + 2 * q) =
                make_float2(o_[t][nt][2] * il1, o_[t][nt][3] * il1);
        }
    }
}

static const int SMEM_BYTES = (2 * 64 * KSTR + 2 * 64 * VSTR + 4 * 32 * PSTR) * 4 + 128;

extern "C" void kernel_launch(void* const* d_in, const int* in_sizes, int n_in,
                              void* d_out, int out_size) {
    const float* Q = (const float*)d_in[0];
    const float* K = (const float*)d_in[1];
    const float* V = (const float*)d_in[2];
    const int* qm_b = (const int*)d_in[3];
    const int* qm_s = (const int*)d_in[4];
    const int* km_b = (const int*)d_in[5];
    const int* km_s = (const int*)d_in[6];
    float* O = (float*)d_out;

    cudaFuncSetAttribute(attn_kernel, cudaFuncAttributeMaxDynamicSharedMemorySize, SMEM_BYTES);

    zero_masks_kernel<<<(B_ * S_ + 255) / 256, 256>>>();
    scatter_masks_kernel<<<(M_ + 255) / 256, 256>>>(qm_b, qm_s, km_b, km_s);

    // pre-round K and V to tf32 (RNA) once per launch
    float* Ktf_p;  cudaGetSymbolAddress((void**)&Ktf_p, g_Ktf);
    float* Vtf_p;  cudaGetSymbolAddress((void**)&Vtf_p, g_Vtf);
    tf32_round_kernel<<<(NELEM / 4 + 255) / 256, 256>>>((const float4*)K, (uint4*)Ktf_p);
    tf32_round_kernel<<<(NELEM / 4 + 255) / 256, 256>>>((const float4*)V, (uint4*)Vtf_p);

    attn_kernel<<<B_ * H_ * (S_ / 128), 128, SMEM_BYTES>>>(Q, O);
}

// round 14
// speedup vs baseline: 1.0079x; 1.0023x over previous
#include <cuda_runtime.h>
#include <stdint.h>
#include <math.h>

#define B_ 8
#define S_ 1024
#define H_ 16
#define D_ 64
#define M_ 1024
#define HD (H_ * D_)
#define NELEM (B_ * S_ * H_ * D_)

#define KSTR 68  // K smem stride: B-frag bank = 4g+q  -> conflict-free
#define VSTR 72  // V smem stride: B-frag bank = 8q+g  -> conflict-free
#define PSTR 68  // P smem stride: A-frag bank = 4g+q  -> conflict-free

__device__ unsigned char g_rowmask[B_ * S_];
__device__ unsigned char g_colmask[B_ * S_];
__device__ float g_Ktf[NELEM];  // tf32-rounded K
__device__ float g_Vtf[NELEM];  // tf32-rounded V

__global__ void zero_masks_kernel() {
    int i = blockIdx.x * blockDim.x + threadIdx.x;
    if (i < B_ * S_) {
        g_rowmask[i] = 0;
        g_colmask[i] = 0;
    }
}

__global__ void scatter_masks_kernel(const int* __restrict__ qm_b, const int* __restrict__ qm_s,
                                     const int* __restrict__ km_b, const int* __restrict__ km_s) {
    int i = blockIdx.x * blockDim.x + threadIdx.x;
    if (i < M_) {
        g_rowmask[qm_b[i] * S_ + qm_s[i]] = 1;
        g_colmask[km_b[i] * S_ + km_s[i]] = 1;
    }
}

__device__ __forceinline__ unsigned f2tf(float x) {
    unsigned u;
    asm("cvt.rna.tf32.f32 %0, %1;" : "=r"(u) : "f"(x));
    return u;
}

// Pre-round a tensor to tf32 (RNA), vectorized.
__global__ void tf32_round_kernel(const float4* __restrict__ src, uint4* __restrict__ dst) {
    int i = blockIdx.x * blockDim.x + threadIdx.x;
    if (i < NELEM / 4) {
        float4 v = src[i];
        uint4 u;
        u.x = f2tf(v.x); u.y = f2tf(v.y); u.z = f2tf(v.z); u.w = f2tf(v.w);
        dst[i] = u;
    }
}

__device__ __forceinline__ void mma8(float& c0, float& c1, float& c2, float& c3,
                                     unsigned a0, unsigned a1, unsigned a2, unsigned a3,
                                     unsigned b0, unsigned b1) {
    asm volatile(
        "mma.sync.aligned.m16n8k8.row.col.f32.tf32.tf32.f32 "
        "{%0,%1,%2,%3}, {%4,%5,%6,%7}, {%8,%9}, {%0,%1,%2,%3};"
        : "+f"(c0), "+f"(c1), "+f"(c2), "+f"(c3)
        : "r"(a0), "r"(a1), "r"(a2), "r"(a3), "r"(b0), "r"(b1));
}

__device__ __forceinline__ void cp16(const void* smem_dst, const void* gmem_src) {
    unsigned daddr = (unsigned)__cvta_generic_to_shared(smem_dst);
    asm volatile("cp.async.ca.shared.global [%0], [%1], 16;" :: "r"(daddr), "l"(gmem_src));
}

// Flash attention, tf32 mma.sync, 32-row warp tiles, cp.async double-buffered
// staging of PRE-ROUNDED K/V (no cvt in the hot loops).
__global__ __launch_bounds__(128, 2) void attn_kernel(const float* __restrict__ Q,
                                                      float* __restrict__ O) {
    extern __shared__ float smem[];
    float* Kbuf[2] = { smem, smem + 64 * KSTR };
    float* Vbuf[2] = { smem + 2 * 64 * KSTR, smem + 2 * 64 * KSTR + 64 * VSTR };
    float* Ps = smem + 2 * 64 * KSTR + 2 * 64 * VSTR;          // 4 * 32 * PSTR
    unsigned char* CmB = (unsigned char*)(Ps + 4 * 32 * PSTR); // 2 * 64

    const int bid = blockIdx.x;
    const int qt = bid & 7;
    const int h  = (bid >> 3) & 15;
    const int b  = bid >> 7;
    const int tid = threadIdx.x;
    const int w = tid >> 5, lane = tid & 31;
    const int g = lane >> 2, q = lane & 3;

    float* Pw = Ps + w * (32 * PSTR);
    const int row0 = qt * 128 + w * 32;

    const float* Kb = g_Ktf + (size_t)b * S_ * HD + h * D_;
    const float* Vb = g_Vtf + ((size_t)b * H_ + h) * S_ * D_;

    // ---- prologue: stage tile 0 into buffer 0 ----
    {
        #pragma unroll
        for (int i = 0; i < 8; ++i) {
            int idx = i * 128 + tid;
            int c4 = idx >> 6, s = idx & 63;
            cp16(&Kbuf[0][s * KSTR + 4 * c4], Kb + (size_t)s * HD + 4 * c4);
            cp16(&Vbuf[0][s * VSTR + 4 * c4], Vb + (size_t)s * D_ + 4 * c4);
        }
        if (tid < 4)
            cp16(CmB + 16 * tid, g_colmask + b * S_ + 16 * tid);
        asm volatile("cp.async.commit_group;");
    }

    // ---- Q fragments for both row-tiles (scale 1/8 folded, tf32 RNA) ----
    unsigned qf[2][8][4];
    #pragma unroll
    for (int t = 0; t < 2; ++t) {
        const float* Qb = Q + ((size_t)(b * S_ + row0 + 16 * t + g)) * HD + h * D_;
        #pragma unroll
        for (int ks = 0; ks < 8; ++ks) {
            qf[t][ks][0] = f2tf(Qb[ks * 8 + q] * 0.125f);
            qf[t][ks][1] = f2tf(Qb[(size_t)8 * HD + ks * 8 + q] * 0.125f);
            qf[t][ks][2] = f2tf(Qb[ks * 8 + q + 4] * 0.125f);
            qf[t][ks][3] = f2tf(Qb[(size_t)8 * HD + ks * 8 + q + 4] * 0.125f);
        }
    }
    int rm[2][2];
    #pragma unroll
    for (int t = 0; t < 2; ++t) {
        rm[t][0] = g_rowmask[b * S_ + row0 + 16 * t + g];
        rm[t][1] = g_rowmask[b * S_ + row0 + 16 * t + g + 8];
    }

    float o_[2][8][4];
    #pragma unroll
    for (int t = 0; t < 2; ++t)
        #pragma unroll
        for (int nt = 0; nt < 8; ++nt)
            o_[t][nt][0] = o_[t][nt][1] = o_[t][nt][2] = o_[t][nt][3] = 0.f;
    float m_[2][2], l_[2][2];
    #pragma unroll
    for (int t = 0; t < 2; ++t) { m_[t][0] = m_[t][1] = -INFINITY; l_[t][0] = l_[t][1] = 0.f; }

    for (int kt = 0; kt < 16; ++kt) {
        const int cur = kt & 1;
        asm volatile("cp.async.wait_group 0;");
        __syncthreads();  // current tile visible; prev buffer reads done

        // ---- prefetch next tile into the other buffer ----
        if (kt + 1 < 16) {
            const int nxt = cur ^ 1;
            #pragma unroll
            for (int i = 0; i < 8; ++i) {
                int idx = i * 128 + tid;
                int c4 = idx >> 6, s = idx & 63;
                cp16(&Kbuf[nxt][s * KSTR + 4 * c4],
                     Kb + (size_t)((kt + 1) * 64 + s) * HD + 4 * c4);
                cp16(&Vbuf[nxt][s * VSTR + 4 * c4],
                     Vb + (size_t)((kt + 1) * 64 + s) * D_ + 4 * c4);
            }
            if (tid < 4)
                cp16(CmB + 64 * nxt + 16 * tid,
                     g_colmask + b * S_ + (kt + 1) * 64 + 16 * tid);
            asm volatile("cp.async.commit_group;");
        }

        const float* Ksb = Kbuf[cur];
        const float* Vsb = Vbuf[cur];
        const unsigned char* Cm = CmB + 64 * cur;

        // ---- S = Q K^T : B-frags shared by both row-tiles (no cvt!) ----
        float s0[8][4], s1[8][4];
        #pragma unroll
        for (int nt = 0; nt < 8; ++nt) {
            s0[nt][0] = s0[nt][1] = s0[nt][2] = s0[nt][3] = 0.f;
            s1[nt][0] = s1[nt][1] = s1[nt][2] = s1[nt][3] = 0.f;
        }
        #pragma unroll
        for (int ks = 0; ks < 8; ++ks) {
            #pragma unroll
            for (int nt = 0; nt < 8; ++nt) {
                const float* kp = &Ksb[(nt * 8 + g) * KSTR + ks * 8 + q];
                unsigned b0 = __float_as_uint(kp[0]);
                unsigned b1 = __float_as_uint(kp[4]);
                mma8(s0[nt][0], s0[nt][1], s0[nt][2], s0[nt][3],
                     qf[0][ks][0], qf[0][ks][1], qf[0][ks][2], qf[0][ks][3], b0, b1);
                mma8(s1[nt][0], s1[nt][1], s1[nt][2], s1[nt][3],
                     qf[1][ks][0], qf[1][ks][1], qf[1][ks][2], qf[1][ks][3], b0, b1);
            }
        }

        // ---- mask + online softmax ----
        float al[2][2];
        #pragma unroll
        for (int t = 0; t < 2; ++t) {
            float (*s_)[4] = t ? s1 : s0;
            float tm0 = -INFINITY, tm1 = -INFINITY;
            #pragma unroll
            for (int nt = 0; nt < 8; ++nt) {
                unsigned cc = *(const unsigned short*)(Cm + nt * 8 + 2 * q);
                int c0 = (int)(cc & 0xFFu), c1 = (int)(cc >> 8);
                if (rm[t][0] | c0) s_[nt][0] = -1e10f;
                if (rm[t][0] | c1) s_[nt][1] = -1e10f;
                if (rm[t][1] | c0) s_[nt][2] = -1e10f;
                if (rm[t][1] | c1) s_[nt][3] = -1e10f;
                tm0 = fmaxf(tm0, fmaxf(s_[nt][0], s_[nt][1]));
                tm1 = fmaxf(tm1, fmaxf(s_[nt][2], s_[nt][3]));
            }
            tm0 = fmaxf(tm0, __shfl_xor_sync(0xffffffffu, tm0, 1));
            tm0 = fmaxf(tm0, __shfl_xor_sync(0xffffffffu, tm0, 2));
            tm1 = fmaxf(tm1, __shfl_xor_sync(0xffffffffu, tm1, 1));
            tm1 = fmaxf(tm1, __shfl_xor_sync(0xffffffffu, tm1, 2));
            float mn0 = fmaxf(m_[t][0], tm0), mn1 = fmaxf(m_[t][1], tm1);
            float a0 = __expf(m_[t][0] - mn0), a1 = __expf(m_[t][1] - mn1);
            float ps0 = 0.f, ps1 = 0.f;
            #pragma unroll
            for (int nt = 0; nt < 8; ++nt) {
                s_[nt][0] = __expf(s_[nt][0] - mn0);
                s_[nt][1] = __expf(s_[nt][1] - mn0);
                s_[nt][2] = __expf(s_[nt][2] - mn1);
                s_[nt][3] = __expf(s_[nt][3] - mn1);
                ps0 += s_[nt][0] + s_[nt][1];
                ps1 += s_[nt][2] + s_[nt][3];
            }
            ps0 += __shfl_xor_sync(0xffffffffu, ps0, 1);
            ps0 += __shfl_xor_sync(0xffffffffu, ps0, 2);
            ps1 += __shfl_xor_sync(0xffffffffu, ps1, 1);
            ps1 += __shfl_xor_sync(0xffffffffu, ps1, 2);
            l_[t][0] = l_[t][0] * a0 + ps0;
            l_[t][1] = l_[t][1] * a1 + ps1;
            m_[t][0] = mn0; m_[t][1] = mn1;
            al[t][0] = a0; al[t][1] = a1;
        }
        #pragma unroll
        for (int t = 0; t < 2; ++t)
            #pragma unroll
            for (int nt = 0; nt < 8; ++nt) {
                o_[t][nt][0] *= al[t][0]; o_[t][nt][1] *= al[t][0];
                o_[t][nt][2] *= al[t][1]; o_[t][nt][3] *= al[t][1];
            }

        // ---- P -> warp-private smem (tf32 RNA), consume as A-frags ----
        __syncwarp();
        #pragma unroll
        for (int t = 0; t < 2; ++t) {
            float (*s_)[4] = t ? s1 : s0;
            #pragma unroll
            for (int nt = 0; nt < 8; ++nt) {
                uint2 lo = make_uint2(f2tf(s_[nt][0]), f2tf(s_[nt][1]));
                uint2 hi = make_uint2(f2tf(s_[nt][2]), f2tf(s_[nt][3]));
                *(uint2*)&Pw[(16 * t + g) * PSTR + 8 * nt + 2 * q] = lo;
                *(uint2*)&Pw[(16 * t + g + 8) * PSTR + 8 * nt + 2 * q] = hi;
            }
        }
        __syncwarp();

        // ---- O += P V (no cvt on V) ----
        #pragma unroll
        for (int ks = 0; ks < 8; ++ks) {
            unsigned a[2][4];
            #pragma unroll
            for (int t = 0; t < 2; ++t) {
                const float* pp = &Pw[(16 * t + g) * PSTR + 8 * ks + q];
                a[t][0] = __float_as_uint(pp[0]);
                a[t][1] = __float_as_uint(pp[8 * PSTR]);
                a[t][2] = __float_as_uint(pp[4]);
                a[t][3] = __float_as_uint(pp[8 * PSTR + 4]);
            }
            #pragma unroll
            for (int nt = 0; nt < 8; ++nt) {
                const float* vp = &Vsb[(ks * 8 + q) * VSTR + 8 * nt + g];
                unsigned b0 = __float_as_uint(vp[0]);
                unsigned b1 = __float_as_uint(vp[4 * VSTR]);
                mma8(o_[0][nt][0], o_[0][nt][1], o_[0][nt][2], o_[0][nt][3],
                     a[0][0], a[0][1], a[0][2], a[0][3], b0, b1);
                mma8(o_[1][nt][0], o_[1][nt][1], o_[1][nt][2], o_[1][nt][3],
                     a[1][0], a[1][1], a[1][2], a[1][3], b0, b1);
            }
        }
    }

    // ---- epilogue: normalize + store; O is (B,H,S,D) ----
    float* Ob = O + (((size_t)b * H_ + h) * S_ + row0) * D_;
    #pragma unroll
    for (int t = 0; t < 2; ++t) {
        float il0 = 1.f / l_[t][0], il1 = 1.f / l_[t][1];
        float* r_lo = Ob + (size_t)(16 * t + g) * D_;
        float* r_hi = Ob + (size_t)(16 * t + g + 8) * D_;
        #pragma unroll
        for (int nt = 0; nt < 8; ++nt) {
            *(float2*)(r_lo + 8 * nt + 2 * q) =
                make_float2(o_[t][nt][0] * il0, o_[t][nt][1] * il0);
            *(float2*)(r_hi + 8 * nt + 2 * q) =
                make_float2(o_[t][nt][2] * il1, o_[t][nt][3] * il1);
        }
    }
}

static const int SMEM_BYTES = (2 * 64 * KSTR + 2 * 64 * VSTR + 4 * 32 * PSTR) * 4 + 128;

extern "C" void kernel_launch(void* const* d_in, const int* in_sizes, int n_in,
                              void* d_out, int out_size) {
    const float* Q = (const float*)d_in[0];
    const float* K = (const float*)d_in[1];
    const float* V = (const float*)d_in[2];
    const int* qm_b = (const int*)d_in[3];
    const int* qm_s = (const int*)d_in[4];
    const int* km_b = (const int*)d_in[5];
    const int* km_s = (const int*)d_in[6];
    float* O = (float*)d_out;

    cudaFuncSetAttribute(attn_kernel, cudaFuncAttributeMaxDynamicSharedMemorySize, SMEM_BYTES);

    zero_masks_kernel<<<(B_ * S_ + 255) / 256, 256>>>();
    scatter_masks_kernel<<<(M_ + 255) / 256, 256>>>(qm_b, qm_s, km_b, km_s);

    // pre-round K and V to tf32 (RNA) once per launch
    float* Ktf_p;  cudaGetSymbolAddress((void**)&Ktf_p, g_Ktf);
    float* Vtf_p;  cudaGetSymbolAddress((void**)&Vtf_p, g_Vtf);
    tf32_round_kernel<<<(NELEM / 4 + 255) / 256, 256>>>((const float4*)K, (uint4*)Ktf_p);
    tf32_round_kernel<<<(NELEM / 4 + 255) / 256, 256>>>((const float4*)V, (uint4*)Vtf_p);

    attn_kernel<<<B_ * H_ * (S_ / 128), 128, SMEM_BYTES>>>(Q, O);
}